// round 13
// baseline (speedup 1.0000x reference)
#include <cuda_runtime.h>
#include <stdint.h>

#define BB_ 8
#define HH_ 384
#define WW_ 1280
#define HW_ (HH_*WW_)           /* 491520 */
#define NTOT (BB_*HW_)          /* 3932160 */
#define NPAIRS 4915
#define NGPAIR (BB_*NPAIRS)     /* 39320 */
#define RANK_LO 466943          /* floor(0.95f * (HW-1)) */
#define RANK_HI 466944

#define NBLK (NTOT/256)         /* 15360 */
#define NBLKG ((NGPAIR+255)/256)/* 154 */
#define TB1 (HW_/2048)          /* 240 blocks/batch for tree level build */

/* ---------------- scratch (static device allocs only) ---------------- */
__device__ float g_tmpG[NTOT];
__device__ float g_tmpP[NTOT];
__device__ float g_gt[NTOT];
__device__ float g_pred[NTOT];
__device__ float g_cuml[NTOT];
__device__ float g_tree[NTOT];          /* per-batch tree levels 1..18, 491516 floats used */
__device__ unsigned char g_flags[NTOT];
__device__ unsigned int g_hist1[BB_][65536];
__device__ unsigned int g_hist2[BB_][2][65536];
__device__ int g_binlo[BB_], g_remlo[BB_], g_binhi[BB_], g_remhi[BB_];
__device__ float g_q[BB_];
__device__ int g_invcnt[BB_];
__device__ double g_pl[NBLK], g_pc[NBLK];
__device__ double g_plg[NBLKG], g_pcg[NBLKG];

/* per-batch offsets of tree level L (L=1..18); level L holds the floor-chain count */
__constant__ int c_offs[19] = {
  -1, 0, 245760, 368640, 430080, 460800, 476160, 483840, 487680,
  489600, 490560, 491040, 491280, 491400, 491460, 491490, 491505, 491512, 491515
};

struct Keys {
  unsigned kr1a,kr1b,kr2a,kr2b,kgaa,kgab,kgba,kgbb;
  unsigned pka[BB_], pkb[BB_];
};

/* ---------------- threefry2x32 (JAX-exact, 20 rounds) ---------------- */
__host__ __device__ __forceinline__ unsigned rotl32(unsigned v, int d){
  return (v<<d)|(v>>(32-d));
}
__host__ __device__ inline void tf2x32(unsigned k0, unsigned k1, unsigned c0, unsigned c1,
                                       unsigned &o0, unsigned &o1){
  unsigned ks2 = k0 ^ k1 ^ 0x1BD11BDAu;
  unsigned x0 = c0 + k0;
  unsigned x1 = c1 + k1;
#define TF_R(r) { x0 += x1; x1 = rotl32(x1, r); x1 ^= x0; }
  TF_R(13) TF_R(15) TF_R(26) TF_R(6)
  x0 += k1;  x1 += ks2 + 1u;
  TF_R(17) TF_R(29) TF_R(16) TF_R(24)
  x0 += ks2; x1 += k0 + 2u;
  TF_R(13) TF_R(15) TF_R(26) TF_R(6)
  x0 += k0;  x1 += k1 + 3u;
  TF_R(17) TF_R(29) TF_R(16) TF_R(24)
  x0 += k1;  x1 += ks2 + 4u;
  TF_R(13) TF_R(15) TF_R(26) TF_R(6)
  x0 += ks2; x1 += k0 + 5u;
#undef TF_R
  o0 = x0; o1 = x1;
}
/* partitionable-mode 32-bit random bits: counters (0, i), output o0^o1 */
__device__ __forceinline__ unsigned bits32(unsigned ka, unsigned kb, unsigned idx){
  unsigned o0,o1; tf2x32(ka,kb,0u,idx,o0,o1); return o0^o1;
}
/* partitionable-mode 64-bit random bits: counters (0, i), output (o0<<32)|o1 */
__device__ __forceinline__ unsigned long long bits64(unsigned ka, unsigned kb, unsigned idx){
  unsigned o0,o1; tf2x32(ka,kb,0u,idx,o0,o1);
  return (((unsigned long long)o0) << 32) | (unsigned long long)o1;
}
__device__ __forceinline__ float u01(unsigned bits){
  return __uint_as_float((bits>>9)|0x3f800000u) - 1.0f;
}
__device__ __forceinline__ float softplus_f(float x){
  return fmaxf(x,0.0f) + log1pf(expf(-fabsf(x)));
}

/* ---------------- box filter (separable 5-tap, zero pad, exact f64 accum) ---------------- */
__global__ void k_box_h(const float* __restrict__ dV2, const float* __restrict__ dPr){
  int i = blockIdx.x*256 + threadIdx.x;
  if (i >= NTOT) return;
  int x = i % WW_;
  int rb = i - x;
  double s1 = 0.0, s2 = 0.0;
#pragma unroll
  for (int dx = -2; dx <= 2; ++dx){
    int xx = x + dx;
    if (xx >= 0 && xx < WW_){
      float d = dV2[rb+xx];
      d = (d == 0.0f) ? 1e-5f : d;
      s1 += (double)d;
      s2 += (double)dPr[rb+xx];
    }
  }
  g_tmpG[i] = (float)s1;
  g_tmpP[i] = (float)s2;
}

__global__ void k_box_v(){
  int i = blockIdx.x*256 + threadIdx.x;
  if (i >= NTOT) return;
  int y = (i / WW_) % HH_;
  double s1 = 0.0, s2 = 0.0;
#pragma unroll
  for (int dy = -2; dy <= 2; ++dy){
    int yy = y + dy;
    if (yy >= 0 && yy < HH_){
      int j = i + dy*WW_;
      s1 += (double)g_tmpG[j];
      s2 += (double)g_tmpP[j];
    }
  }
  g_gt[i]   = (float)(s1 * (1.0/25.0));
  g_pred[i] = (float)(s2 * (1.0/25.0));
}

/* ---------------- quantile: radix-select via 2x 16-bit histograms ---------------- */
__global__ void k_hist1(const float* __restrict__ mask){
  int i = blockIdx.x*256 + threadIdx.x;
  if (i >= NTOT) return;
  int b = i / HW_;
  unsigned bits = __float_as_uint(mask[i]);   /* [0,1): bit order == value order */
  atomicAdd(&g_hist1[b][bits>>16], 1u);
}

__device__ void find_rank_dev(const unsigned int* hist, int rank, int* bin_out, int* rem_out){
  __shared__ unsigned int part[256];
  int t = threadIdx.x;
  unsigned s = 0;
  const unsigned int* hp = hist + t*256;
#pragma unroll 8
  for (int j = 0; j < 256; ++j) s += hp[j];
  part[t] = s;
  __syncthreads();
  if (t == 0){
    long cum = 0; int seg = 0;
    while (seg < 256 && cum + (long)part[seg] <= rank){ cum += part[seg]; seg++; }
    long c2 = cum; int j = 0;
    const unsigned int* hq = hist + seg*256;
    while (j < 256 && c2 + (long)hq[j] <= rank){ c2 += hq[j]; j++; }
    *bin_out = seg*256 + j;
    *rem_out = (int)(rank - c2);
  }
  __syncthreads();
}

__global__ void k_findbin1(){
  int b = blockIdx.x;
  find_rank_dev(&g_hist1[b][0], RANK_LO, &g_binlo[b], &g_remlo[b]);
  find_rank_dev(&g_hist1[b][0], RANK_HI, &g_binhi[b], &g_remhi[b]);
}

__global__ void k_hist2(const float* __restrict__ mask){
  int i = blockIdx.x*256 + threadIdx.x;
  if (i >= NTOT) return;
  int b = i / HW_;
  unsigned bits = __float_as_uint(mask[i]);
  int hi = (int)(bits >> 16);
  if (hi == g_binlo[b]) atomicAdd(&g_hist2[b][0][bits & 0xFFFFu], 1u);
  if (hi == g_binhi[b]) atomicAdd(&g_hist2[b][1][bits & 0xFFFFu], 1u);
}

__global__ void k_findbin2(){
  int b = blockIdx.x;
  __shared__ int lo_low, hi_low;
  find_rank_dev(&g_hist2[b][0][0], g_remlo[b], &lo_low, &g_remlo[b]);
  find_rank_dev(&g_hist2[b][1][0], g_remhi[b], &hi_low, &g_remhi[b]);
  if (threadIdx.x == 0){
    float vlo = __uint_as_float(((unsigned)g_binlo[b] << 16) | (unsigned)lo_low);
    float vhi = __uint_as_float(((unsigned)g_binhi[b] << 16) | (unsigned)hi_low);
    /* jnp.quantile 'linear', all-f32, no FMA contraction:
       idx = 0.95f*(n-1); lw = ceil(idx)-idx; hw = idx-floor(idx);
       q = vlo*lw + vhi*hw (lax.add(lax.mul, lax.mul)) */
    float idxf = __fmul_rn(0.95f, (float)(HW_ - 1));
    float lw = __fsub_rn(ceilf(idxf), idxf);
    float hw = __fsub_rn(idxf, floorf(idxf));
    g_q[b] = __fadd_rn(__fmul_rn(vlo, lw), __fmul_rn(vhi, hw));
  }
}

/* ---------------- validity masks (r1, r2 streams, partitionable counters) ---------------- */
__global__ void k_masks(const float* __restrict__ mask, Keys K){
  int i = blockIdx.x*256 + threadIdx.x;
  if (i >= NTOT) return;
  int b = i / HW_;
  float r1 = u01(bits32(K.kr1a, K.kr1b, (unsigned)i));
  float r2 = u01(bits32(K.kr2a, K.kr2b, (unsigned)i));
  bool invt = mask[i] < g_q[b];
  bool inv0 = (r1 < 0.7f) || invt;          /* 1.0 - SAMPLE_RATIO */
  bool valid = !inv0;
  bool invF  = inv0 && (r2 >= 0.3f);        /* 1.0 - LOCAL_SAMPLE_RATIO */
  g_flags[i] = (unsigned char)((valid ? 1 : 0) | (invF ? 2 : 0));
  unsigned bal = __ballot_sync(0xffffffffu, invF);   /* HW % 32 == 0 */
  if ((threadIdx.x & 31) == 0) atomicAdd(&g_invcnt[b], (int)__popc(bal));
}

/* ---------------- tree levels 1..11: exact pairwise sums over aligned 2048 blocks --------- */
__global__ void k_tree1(){
  int blk = blockIdx.x;                 /* 0 .. BB_*TB1-1 */
  int b  = blk / TB1;
  int lb = blk % TB1;
  int leaf0 = lb * 2048;
  int t = threadIdx.x;                  /* 256 threads */
  float pv = 1.0f / fmaxf((float)g_invcnt[b], 1e-9f);
  const unsigned char* fl = g_flags + (size_t)b*HW_ + leaf0;
  float* tr = g_tree + (size_t)b*HW_;

  float v[8];
#pragma unroll
  for (int j = 0; j < 8; ++j) v[j] = (fl[t*8 + j] & 2) ? pv : 0.0f;

  float l1[4];
  l1[0] = v[0]+v[1]; l1[1] = v[2]+v[3]; l1[2] = v[4]+v[5]; l1[3] = v[6]+v[7];
  int p1 = (leaf0 >> 1) + t*4;
#pragma unroll
  for (int j = 0; j < 4; ++j) tr[c_offs[1] + p1 + j] = l1[j];

  float l2a = l1[0]+l1[1], l2b = l1[2]+l1[3];
  int p2 = (leaf0 >> 2) + t*2;
  tr[c_offs[2] + p2]     = l2a;
  tr[c_offs[2] + p2 + 1] = l2b;

  float l3 = l2a + l2b;
  tr[c_offs[3] + (leaf0 >> 3) + t] = l3;

  __shared__ float s[256];
  s[t] = l3;
  __syncthreads();
  int cnt = 256;
  for (int L = 4; L <= 11; ++L){
    cnt >>= 1;
    float nv = 0.0f;
    if (t < cnt) nv = s[2*t] + s[2*t+1];
    __syncthreads();
    if (t < cnt){
      s[t] = nv;
      tr[c_offs[L] + (leaf0 >> L) + t] = nv;
    }
    __syncthreads();
  }
}

/* ---------------- tree levels 12..18 (per batch; floor-halving at odd counts) ------------- */
__global__ void k_tree2(){
  int b = blockIdx.x;
  int t = threadIdx.x;                  /* 128 threads */
  float* tr = g_tree + (size_t)b*HW_;
  __shared__ float s[240];
  for (int i = t; i < 240; i += 128) s[i] = tr[c_offs[11] + i];
  __syncthreads();
  int cnt = 240;
  for (int L = 12; L <= 18; ++L){
    int nc = cnt >> 1;                  /* odd cnt: last element left unpaired */
    float nv = 0.0f;
    if (t < nc) nv = s[2*t] + s[2*t+1];
    __syncthreads();
    if (t < nc){
      s[t] = nv;
      tr[c_offs[L] + t] = nv;
    }
    __syncthreads();
    cnt = nc;
  }
}

/* ------- materialize cuml[j]: left-fold of binary-decomposition tree blocks of (j+1) ------ */
__global__ void k_cuml(){
  int i = blockIdx.x*256 + threadIdx.x;
  if (i >= NTOT) return;
  int b = i / HW_;
  int j = i - b*HW_;
  const float* tr = g_tree + (size_t)b*HW_;
  float pv = 1.0f / fmaxf((float)g_invcnt[b], 1e-9f);
  unsigned m = (unsigned)(j + 1);
  float acc = 0.0f;
  bool first = true;
  int start = 0;
#pragma unroll
  for (int a = 18; a >= 1; --a){
    if (m & (1u << a)){
      float v = tr[c_offs[a] + (start >> a)];
      acc = first ? v : (acc + v);
      first = false;
      start += (1 << a);
    }
  }
  if (m & 1u){
    float v = (g_flags[i] & 2) ? pv : 0.0f;
    acc = first ? v : (acc + v);
  }
  g_cuml[i] = acc;
}

/* ---------------- local ranking loss (choice + gather + softplus) ----------------
   EXPERIMENT (re-run of R11, killed by infra): choice threshold r = p_cuml[-1] * u
   (no (1-u) reflection). */
__global__ void k_local(Keys K){
  int i = blockIdx.x*256 + threadIdx.x;
  int t = threadIdx.x;
  double L = 0.0, C = 0.0;
  if (i < NTOT){
    unsigned char f = g_flags[i];
    if (f & 1){
      int b = i / HW_;
      int pos = i - b*HW_;
      float zb = g_gt[i];
      float Bv = g_pred[i];
      float u = u01(bits32(K.pka[b], K.pkb[b], (unsigned)pos));
      const float* c = g_cuml + (size_t)b*HW_;
      float last = c[HW_-1];
      float r = __fmul_rn(last, u);          /* <-- flipped from last*(1-u) */
      int lo = 0, hi = HW_;
      while (lo < hi){ int mid = (lo+hi) >> 1; if (c[mid] < r) lo = mid+1; else hi = mid; }
      int pp = (lo < HW_) ? lo : (HW_-1);
      float za = g_gt[(size_t)b*HW_ + pp];
      float Av = g_pred[(size_t)b*HW_ + pp];
      float t1 = za/zb, t2 = zb/za;
      float target = (t1 >= 1.15f) ? -1.0f : ((t2 > 1.15f) ? 1.0f : 0.0f);
      if (target != 0.0f){
        L = (double)softplus_f(-target * (Av - Bv));
        C = 1.0;
      }
    }
  }
  __shared__ double sL[256], sC[256];
  sL[t] = L; sC[t] = C;
  __syncthreads();
  for (int off = 128; off > 0; off >>= 1){
    if (t < off){ sL[t] += sL[t+off]; sC[t] += sC[t+off]; }
    __syncthreads();
  }
  if (t == 0){ g_pl[blockIdx.x] = sL[0]; g_pc[blockIdx.x] = sC[0]; }
}

/* ---------------- global ranking loss: x64 randint (int64), partitionable ----------------
   bits = random_bits(key, 64, (2, n)); u64[i] = (o0(0,i)<<32) | o1(0,i)
   hi = bits[0][p] (linear idx p), lo = bits[1][p] (linear idx n+p)
   multiplier = (2^32 % span)^2 % span = 65536   (span = HW = 491520)
   idx = ((hi % span) * 65536 + (lo % span)) % span                              */
__global__ void k_global(Keys K){
  int j = blockIdx.x*256 + threadIdx.x;
  int t = threadIdx.x;
  double L = 0.0, C = 0.0;
  if (j < NGPAIR){
    int b = j / NPAIRS;
    int p = j - b*NPAIRS;
    const unsigned long long span = (unsigned long long)HW_;
    unsigned long long hia = bits64(K.kgaa, K.kgab, (unsigned)p);
    unsigned long long loa = bits64(K.kgaa, K.kgab, (unsigned)(NPAIRS + p));
    unsigned long long hib = bits64(K.kgba, K.kgbb, (unsigned)p);
    unsigned long long lob = bits64(K.kgba, K.kgbb, (unsigned)(NPAIRS + p));
    int ia = (int)((((hia % span) * 65536ull) + (loa % span)) % span);
    int ib = (int)((((hib % span) * 65536ull) + (lob % span)) % span);
    float za = g_gt[(size_t)b*HW_ + ia];
    float zb = g_gt[(size_t)b*HW_ + ib];
    float Av = g_pred[(size_t)b*HW_ + ia];
    float Bv = g_pred[(size_t)b*HW_ + ib];
    bool ign = (za > 1e-8f) || (zb > 1e-8f);
    float t1 = za/zb, t2 = zb/za;
    float target = (t1 > 1.15f) ? -1.0f : ((t2 > 1.15f) ? 1.0f : 0.0f);  /* strict > */
    if (ign && target != 0.0f){
      L = (double)softplus_f(-target * (Av - Bv));
      C = 1.0;
    }
  }
  __shared__ double sL[256], sC[256];
  sL[t] = L; sC[t] = C;
  __syncthreads();
  for (int off = 128; off > 0; off >>= 1){
    if (t < off){ sL[t] += sL[t+off]; sC[t] += sC[t+off]; }
    __syncthreads();
  }
  if (t == 0){ g_plg[blockIdx.x] = sL[0]; g_pcg[blockIdx.x] = sC[0]; }
}

/* ---------------- deterministic final reduction ---------------- */
__global__ void k_final(float* __restrict__ out){
  int t = threadIdx.x;
  double L = 0.0, C = 0.0;
  for (int i = t; i < NBLK;  i += 256){ L += g_pl[i];  C += g_pc[i];  }
  for (int i = t; i < NBLKG; i += 256){ L += g_plg[i]; C += g_pcg[i]; }
  __shared__ double sL[256], sC[256];
  sL[t] = L; sC[t] = C;
  __syncthreads();
  for (int off = 128; off > 0; off >>= 1){
    if (t < off){ sL[t] += sL[t+off]; sC[t] += sC[t+off]; }
    __syncthreads();
  }
  if (t == 0) out[0] = (float)(sL[0] / sC[0]);
}

/* ---------------- launch ---------------- */
extern "C" void kernel_launch(void* const* d_in, const int* in_sizes, int n_in,
                              void* d_out, int out_size){
  (void)in_sizes; (void)n_in; (void)out_size;
  const float* dV2   = (const float*)d_in[0];
  const float* dPred = (const float*)d_in[1];
  const float* dMask = (const float*)d_in[2];
  float* out = (float*)d_out;

  /* partitionable split: key_j = threefry(root, (0, j)), full 2-word output */
  Keys K;
  unsigned o0, o1;
  tf2x32(0u, 42u, 0u, 0u, o0, o1); K.kr1a = o0; K.kr1b = o1;   /* k_r1  */
  tf2x32(0u, 42u, 0u, 1u, o0, o1); K.kr2a = o0; K.kr2b = o1;   /* k_r2  */
  unsigned kpa, kpb;
  tf2x32(0u, 42u, 0u, 2u, kpa, kpb);                            /* k_part */
  tf2x32(0u, 42u, 0u, 3u, o0, o1); K.kgaa = o0; K.kgab = o1;   /* k_ga  */
  tf2x32(0u, 42u, 0u, 4u, o0, o1); K.kgba = o0; K.kgbb = o1;   /* k_gb  */
  for (unsigned b = 0; b < BB_; ++b){
    tf2x32(kpa, kpb, 0u, b, o0, o1);
    K.pka[b] = o0; K.pkb[b] = o1;
  }

  void *p1, *p2, *p3;
  cudaGetSymbolAddress(&p1, g_hist1);
  cudaGetSymbolAddress(&p2, g_hist2);
  cudaGetSymbolAddress(&p3, g_invcnt);
  cudaMemsetAsync(p1, 0, (size_t)BB_*65536*sizeof(unsigned int), 0);
  cudaMemsetAsync(p2, 0, (size_t)BB_*2*65536*sizeof(unsigned int), 0);
  cudaMemsetAsync(p3, 0, (size_t)BB_*sizeof(int), 0);

  k_box_h   <<<NBLK, 256>>>(dV2, dPred);
  k_box_v   <<<NBLK, 256>>>();
  k_hist1   <<<NBLK, 256>>>(dMask);
  k_findbin1<<<BB_, 256>>>();
  k_hist2   <<<NBLK, 256>>>(dMask);
  k_findbin2<<<BB_, 256>>>();
  k_masks   <<<NBLK, 256>>>(dMask, K);
  k_tree1   <<<BB_*TB1, 256>>>();
  k_tree2   <<<BB_, 128>>>();
  k_cuml    <<<NBLK, 256>>>();
  k_local   <<<NBLK, 256>>>(K);
  k_global  <<<NBLKG, 256>>>(K);
  k_final   <<<1, 256>>>(out);
}